// round 16
// baseline (speedup 1.0000x reference)
#include <cuda_runtime.h>
#include <math.h>

#define NB 2
#define MB 16384
#define PB 5023
#define KB 4
#define CB 32
#define HPX 256
#define REG 129
#define ROFF 127
#define NQ (NB*MB)
#define NR (NQ*KB)
#define G 8
#define NC (G*G*G)

#define DENS_OFF 0
#define RGB_OFF  (NQ)
#define DIST_OFF (NQ + NQ*32)

typedef unsigned long long ull;

// ---------------- device scratch ----------------
__device__ __align__(16) float4 g_pts4[NB*PB];
__device__ __align__(16) float4 g_cellpts[NB*PB];
__device__ int g_cellstart[NB][NC+1];
__device__ __align__(16) float  g_texT[NB*3*REG*REG*CB];
__device__ __align__(16) float  g_knn_d[NQ*KB];
__device__ int    g_knn_i[NQ*KB];
__device__ float  g_wpart[128*4];
__device__ float  g_wsum[NB*KB];
__device__ __align__(16) float  g_pin[NR*64];
__device__ __align__(16) float  g_ph1[NR*64];
__device__ __align__(16) float  g_ph2[NR*32];
__device__ __align__(16) float  g_feat[NQ*64];
__device__ __align__(16) float  g_h1[NQ*128];
__device__ __align__(16) float  g_h2[NQ*128];
__device__ __align__(16) float  g_h3[NQ*128];
__device__ __align__(16) float  g_rin[NQ*160];
__device__ __align__(16) float  g_hr[NQ*64];

// ---------------- helpers ----------------
__device__ __forceinline__ unsigned f2ord(float f){
    unsigned b = __float_as_uint(f);
    return (b & 0x80000000u) ? ~b : (b | 0x80000000u);
}
__device__ __forceinline__ float ord2f(unsigned u){
    unsigned b = (u & 0x80000000u) ? (u & 0x7fffffffu) : ~u;
    return __uint_as_float(b);
}
__device__ __forceinline__ ull umin64(ull a, ull b){ return a<b?a:b; }
__device__ __forceinline__ ull umax64(ull a, ull b){ return a>b?a:b; }
__device__ __forceinline__ void insert4(ull& k0, ull& k1, ull& k2, ull& k3, ull c){
    ull mn2 = umin64(k2,c), mn1 = umin64(k1,c), mn0 = umin64(k0,c);
    k3 = umax64(k2,c); k2 = umax64(k1,mn2); k1 = umax64(k0,mn1); k0 = mn0;
}
__device__ __forceinline__ int cellof(float x){
    int c = (int)(x * (float)G);
    return min(G-1, max(0, c));
}
__device__ __forceinline__ unsigned f2tf(float f){
    unsigned r;
    asm("cvt.rna.tf32.f32 %0, %1;" : "=r"(r) : "f"(f));
    return r;
}

// ---------------- K1: pack points ----------------
__global__ void k_prep(const float* __restrict__ ppos){
    int i = blockIdx.x*blockDim.x + threadIdx.x;
    if (i < NB*PB){
        float x = ppos[3*i+0], y = ppos[3*i+1], z = ppos[3*i+2];
        g_pts4[i] = make_float4(x,y,z, x*x+y*y+z*z);
    }
}

// ---------------- K1b: build uniform grid ----------------
__global__ __launch_bounds__(512) void k_build(const float* __restrict__ ppos){
    __shared__ int s_cnt[NC];
    __shared__ int s_off[NC];
    int n = blockIdx.x, t = threadIdx.x;
    s_cnt[t] = 0;
    __syncthreads();
    for (int i = t; i < PB; i += 512){
        const float* p = ppos + (size_t)(n*PB+i)*3;
        int c = (cellof(p[2])*G + cellof(p[1]))*G + cellof(p[0]);
        atomicAdd(&s_cnt[c], 1);
    }
    __syncthreads();
    for (int ofs=1; ofs<NC; ofs<<=1){
        int add = (t >= ofs) ? s_cnt[t-ofs] : 0;
        __syncthreads();
        s_cnt[t] += add;
        __syncthreads();
    }
    s_off[t] = (t==0) ? 0 : s_cnt[t-1];
    g_cellstart[n][t+1] = s_cnt[t];
    if (t==0) g_cellstart[n][0] = 0;
    __syncthreads();
    for (int i = t; i < PB; i += 512){
        const float* p = ppos + (size_t)(n*PB+i)*3;
        float x=p[0], y=p[1], z=p[2];
        int c = (cellof(z)*G + cellof(y))*G + cellof(x);
        int pos = atomicAdd(&s_off[c], 1);
        g_cellpts[n*PB+pos] = make_float4(x,y,z, __uint_as_float((unsigned)i));
    }
}

// ---------------- grid KNN scan (global candidate reads, L1/L2 resident) ----------------
__device__ __forceinline__ void scan_block(const float4* __restrict__ pts,
                                           const int* __restrict__ s_cs,
                                           float cx, float cy, float cz,
                                           int qcx, int qcy, int qcz, int R,
                                           ull& k0, ull& k1, ull& k2, ull& k3){
    k0=k1=k2=k3=~0ull;
    int z0=max(qcz-R,0), z1=min(qcz+R,G-1);
    int y0=max(qcy-R,0), y1=min(qcy+R,G-1);
    int x0=max(qcx-R,0), x1=min(qcx+R,G-1);
    for (int zz=z0; zz<=z1; ++zz)
        for (int yy=y0; yy<=y1; ++yy){
            int b = (zz*G+yy)*G;
            int j1 = s_cs[b+x1+1];
            for (int j=s_cs[b+x0]; j<j1; ++j){
                float4 p = __ldg(&pts[j]);
                float ddx=cx-p.x, ddy=cy-p.y, ddz=cz-p.z;
                float t = ddx*ddx;
                t = fmaf(ddy,ddy,t);
                t = fmaf(ddz,ddz,t);
                ull key = ((ull)f2ord(t) << 32) | __float_as_uint(p.w);
                if (key < k3) insert4(k0,k1,k2,k3,key);
            }
        }
}
__device__ __forceinline__ float safe_r(float cx, float cy, float cz,
                                        int qcx, int qcy, int qcz, int R){
    const float CS = 1.f/(float)G;
    float rs = 1e30f;
    if (qcx-R > 0)   rs = fminf(rs, cx - (float)(qcx-R)*CS);
    if (qcx+R < G-1) rs = fminf(rs, (float)(qcx+R+1)*CS - cx);
    if (qcy-R > 0)   rs = fminf(rs, cy - (float)(qcy-R)*CS);
    if (qcy+R < G-1) rs = fminf(rs, (float)(qcy+R+1)*CS - cy);
    if (qcz-R > 0)   rs = fminf(rs, cz - (float)(qcz-R)*CS);
    if (qcz+R < G-1) rs = fminf(rs, (float)(qcz+R+1)*CS - cz);
    return rs;
}

// ---------------- K3: grid KNN + fused point-MLP input-row build ----------------
__global__ __launch_bounds__(256) void k_knng(const float* __restrict__ coords,
                                              const float* __restrict__ emb,
                                              float* __restrict__ out){
    __shared__ int s_cs[NC+1];
    int n = blockIdx.x >> 6;
    int t = threadIdx.x;
    const float4* pts = g_cellpts + n*PB;
    for (int i = t; i <= NC; i += 256) s_cs[i] = g_cellstart[n][i];
    __syncthreads();

    int q = blockIdx.x*256 + t;
    float cx = coords[3*q+0], cy = coords[3*q+1], cz = coords[3*q+2];
    int qcx = cellof(cx), qcy = cellof(cy), qcz = cellof(cz);

    ull k0,k1,k2,k3;
    int R = 1;
    scan_block(pts, s_cs, cx,cy,cz, qcx,qcy,qcz, R, k0,k1,k2,k3);
    float d3 = ord2f((unsigned)(k3 >> 32));
    float rs = safe_r(cx,cy,cz, qcx,qcy,qcz, R);
    while (!(d3 <= rs*rs) && R < G){
        ++R;
        scan_block(pts, s_cs, cx,cy,cz, qcx,qcy,qcz, R, k0,k1,k2,k3);
        d3 = ord2f((unsigned)(k3 >> 32));
        rs = safe_r(cx,cy,cz, qcx,qcy,qcz, R);
    }

    ull rr[4] = {k0,k1,k2,k3};
    #pragma unroll
    for (int r=0; r<4; ++r){
        float d  = ord2f((unsigned)(rr[r] >> 32));
        int idx  = (int)(unsigned)rr[r];
        g_knn_d[q*4+r]  = d;
        g_knn_i[q*4+r]  = idx;
        out[DIST_OFF + q*4+r] = d;

        float4 p = __ldg(&g_pts4[n*PB + idx]);
        float rx = cx-p.x, ry = cy-p.y, rz = cz-p.z;
        float inv = rsqrtf(fmaxf(rx*rx+ry*ry+rz*rz, 1e-24f));
        rx *= inv; ry *= inv; rz *= inv;
        float* dst = g_pin + (size_t)(q*4+r)*64;
        const float4* e4 = (const float4*)(emb + (size_t)idx*32);
        #pragma unroll
        for (int i=0;i<8;++i) ((float4*)dst)[i] = __ldg(&e4[i]);
        float comp[3] = {rx,ry,rz};
        #pragma unroll
        for (int c=0;c<3;++c){
            float base = comp[c];
            #pragma unroll
            for (int f=0;f<4;++f){
                float a = base * (float)(1<<f);
                dst[32 + c*4+f] = __sinf(a);
                dst[44 + c*4+f] = __cosf(a);
            }
        }
        dst[56]=rx; dst[57]=ry; dst[58]=rz;
        dst[59]=0.f; dst[60]=0.f; dst[61]=0.f; dst[62]=0.f; dst[63]=0.f;
    }
}

// ---------------- K-TMMA: tf32 tensor-core GEMM ----------------
template<int I, int IW, int O, int MODE>
__global__ __launch_bounds__(256) void k_tmma(const float* __restrict__ A,
                                              const float* __restrict__ W,
                                              const float* __restrict__ Bv,
                                              float* __restrict__ Out){
    const int SA = 36;
    const int SW = O + 8;
    const int NF = O/8;
    __shared__ __align__(16) unsigned s_a[128*SA];
    __shared__ __align__(16) unsigned s_w[32*SW];
    __shared__ float s_b[O];
    const int t = threadIdx.x;
    const int w = t >> 5, lane = t & 31;
    const int grp = lane >> 2, tig = lane & 3;
    for (int i=t;i<O;i+=256) s_b[i]=Bv[i];

    float c[NF][4];
    #pragma unroll
    for (int nf=0;nf<NF;++nf){ c[nf][0]=0.f; c[nf][1]=0.f; c[nf][2]=0.f; c[nf][3]=0.f; }

    int rb = blockIdx.x * 128;

    for (int kc=0; kc<I/32; ++kc){
        __syncthreads();
        #pragma unroll
        for (int r=0;r<4;++r){
            int e = r*256 + t;
            int row = e >> 3, v = e & 7;
            float4 av = __ldg((const float4*)(A + (size_t)(rb+row)*I + kc*32) + v);
            *(uint4*)&s_a[row*SA + v*4] =
                make_uint4(f2tf(av.x), f2tf(av.y), f2tf(av.z), f2tf(av.w));
        }
        #pragma unroll
        for (int e=t; e<32*O/4; e+=256){
            int row = (e*4)/O;
            int col = (e*4)%O;
            int wrow = kc*32 + row;
            float4 wv = make_float4(0.f,0.f,0.f,0.f);
            if (wrow < IW) wv = __ldg((const float4*)(W + (size_t)wrow*O + col));
            *(uint4*)&s_w[row*SW + col] =
                make_uint4(f2tf(wv.x), f2tf(wv.y), f2tf(wv.z), f2tf(wv.w));
        }
        __syncthreads();
        #pragma unroll
        for (int k8=0;k8<4;++k8){
            unsigned a0 = s_a[(w*16+grp  )*SA + k8*8+tig  ];
            unsigned a1 = s_a[(w*16+grp+8)*SA + k8*8+tig  ];
            unsigned a2 = s_a[(w*16+grp  )*SA + k8*8+tig+4];
            unsigned a3 = s_a[(w*16+grp+8)*SA + k8*8+tig+4];
            #pragma unroll
            for (int nf=0;nf<NF;++nf){
                unsigned b0 = s_w[(k8*8+tig  )*SW + nf*8+grp];
                unsigned b1 = s_w[(k8*8+tig+4)*SW + nf*8+grp];
                asm volatile("mma.sync.aligned.m16n8k8.row.col.f32.tf32.tf32.f32 "
                    "{%0,%1,%2,%3}, {%4,%5,%6,%7}, {%8,%9}, {%0,%1,%2,%3};"
                    : "+f"(c[nf][0]),"+f"(c[nf][1]),"+f"(c[nf][2]),"+f"(c[nf][3])
                    : "r"(a0),"r"(a1),"r"(a2),"r"(a3),"r"(b0),"r"(b1));
            }
        }
    }
    int r0 = rb + w*16 + grp;
    int r1 = r0 + 8;
    #pragma unroll
    for (int nf=0;nf<NF;++nf){
        int o = nf*8 + 2*tig;
        float bx = s_b[o], by = s_b[o+1];
        float v0=c[nf][0]+bx, v1=c[nf][1]+by, v2=c[nf][2]+bx, v3=c[nf][3]+by;
        if (MODE==1){ v0=fmaxf(v0,0.f); v1=fmaxf(v1,0.f); v2=fmaxf(v2,0.f); v3=fmaxf(v3,0.f); }
        *(float2*)&Out[(size_t)r0*O+o] = make_float2(v0,v1);
        *(float2*)&Out[(size_t)r1*O+o] = make_float2(v2,v3);
    }
}

// ---------------- K4: wsum ----------------
__global__ __launch_bounds__(256) void k_wsum1(){
    int t = threadIdx.x;
    int base = blockIdx.x * 1024;
    float acc = 0.f;
    #pragma unroll
    for (int r=0;r<4;++r) acc += 1.0f / g_knn_d[base + t + r*256];
    acc += __shfl_xor_sync(0xffffffffu, acc, 4);
    acc += __shfl_xor_sync(0xffffffffu, acc, 8);
    acc += __shfl_xor_sync(0xffffffffu, acc, 16);
    __shared__ float s_p[8][4];
    int w = t >> 5, l = t & 31;
    if (l < 4) s_p[w][l] = acc;
    __syncthreads();
    if (t < 4){
        float s = 0.f;
        #pragma unroll
        for (int w2=0; w2<8; ++w2) s += s_p[w2][t];
        g_wpart[blockIdx.x*4 + t] = s;
    }
}
__global__ void k_wsum2(){
    int t = threadIdx.x;
    if (t < NB*KB){
        int n = t >> 2, kk = t & 3;
        float s = 0.f;
        for (int b = n*64; b < n*64+64; ++b) s += g_wpart[b*4 + kk];
        g_wsum[t] = s;
    }
}

// ---------------- K-combine ----------------
__global__ __launch_bounds__(256) void k_combine(){
    int w = threadIdx.x >> 5, lane = threadIdx.x & 31;
    int q = blockIdx.x*8 + w;
    int n = q / MB;
    float acc = 0.f;
    #pragma unroll
    for (int k=0;k<4;++k){
        float d  = g_knn_d[q*4+k];
        float wk = (1.0f/d) * (1.0f/g_wsum[n*KB+k]);
        acc = fmaf(g_ph2[(size_t)(q*4+k)*32 + lane], wk, acc);
    }
    g_feat[q*64 + 32 + lane] = acc;
}

// ---------------- K2: transpose triplane region ----------------
__global__ void k_transpose(const float* __restrict__ tpl){
    __shared__ float tile[32][33];
    int z  = blockIdx.z;
    int ry = blockIdx.y;
    int xt = blockIdx.x*32;
    int tx = threadIdx.x, ty = threadIdx.y;
    int gx = xt + tx;
    if (gx < REG)
        tile[ty][tx] = tpl[(z*CB + ty)*(HPX*HPX) + (ROFF+ry)*HPX + (ROFF+gx)];
    __syncthreads();
    int xo = xt + ty;
    if (xo < REG)
        g_texT[((z*REG + ry)*REG + xo)*CB + tx] = tile[tx][ty];
}

// ---------------- K5: triplane sampling ----------------
__global__ __launch_bounds__(256) void k_tex(const float* __restrict__ coords){
    int q = blockIdx.x*8 + (threadIdx.x >> 5);
    int lane = threadIdx.x & 31;
    int n = q / MB;
    float c0 = __ldg(&coords[3*q+0]);
    float c1 = __ldg(&coords[3*q+1]);
    float c2 = __ldg(&coords[3*q+2]);
    float gxs[3] = {c0, c0, c2};
    float gys[3] = {c1, c2, c0};
    float acc = 0.f;
    #pragma unroll
    for (int pl=0; pl<3; ++pl){
        float x = (gxs[pl]+1.f)*(HPX*0.5f) - 0.5f;
        float y = (gys[pl]+1.f)*(HPX*0.5f) - 0.5f;
        float fx0 = floorf(x), fy0 = floorf(y);
        int ix0 = (int)fx0, iy0 = (int)fy0;
        float wx1 = x - fx0, wx0 = 1.f - wx1;
        float wy1 = y - fy0, wy0 = 1.f - wy1;
        const float* base = g_texT + (size_t)(n*3 + pl)*REG*REG*CB;
        #pragma unroll
        for (int dy=0; dy<2; ++dy)
            #pragma unroll
            for (int dx=0; dx<2; ++dx){
                int ix = ix0 + dx, iy = iy0 + dy;
                bool v = (ix>=0) & (ix<HPX) & (iy>=0) & (iy<HPX);
                int rx = min(max(ix-ROFF,0), REG-1);
                int ry = min(max(iy-ROFF,0), REG-1);
                float w = (dx?wx1:wx0) * (dy?wy1:wy0) * (v?1.f:0.f);
                acc = fmaf(w, base[(ry*REG + rx)*CB + lane], acc);
            }
    }
    g_feat[q*64 + lane] = acc * (1.f/3.f);
}

// ---------------- K-rin: build rgb input rows [NQ,160] + density head ----------------
__global__ __launch_bounds__(256) void k_rin(const float* __restrict__ coords,
                                             const float* __restrict__ dirs,
                                             const float* __restrict__ dw,
                                             const float* __restrict__ db,
                                             float* __restrict__ out){
    int w = threadIdx.x >> 5, lane = threadIdx.x & 31;
    int q = blockIdx.x*8 + w;

    float4 f4 = *(const float4*)&g_h3[(size_t)q*128 + lane*4];
    *(float4*)&g_rin[(size_t)q*160 + lane*4] = f4;

    float part = f4.x*__ldg(&dw[lane*4+0]) + f4.y*__ldg(&dw[lane*4+1])
               + f4.z*__ldg(&dw[lane*4+2]) + f4.w*__ldg(&dw[lane*4+3]);
    #pragma unroll
    for (int s=16;s>0;s>>=1) part += __shfl_xor_sync(0xffffffffu, part, s);
    if (lane == 0){
        float x = 10.f*(part + __ldg(&db[0]));
        float sp = (x > 20.f) ? x : log1pf(__expf(x));
        float c0=__ldg(&coords[3*q+0]), c1=__ldg(&coords[3*q+1]), c2=__ldg(&coords[3*q+2]);
        bool sel = (c0>-1.f)&&(c0<1.f)&&(c1>-1.f)&&(c1<1.f)&&(c2>-1.f)&&(c2<1.f);
        float raw = (sp*0.1f) * (sel?1.f:0.f);
        out[DENS_OFF + q] = 1.f - __expf(-raw);
    }

    float dx=__ldg(&dirs[3*q+0]), dy=__ldg(&dirs[3*q+1]), dz=__ldg(&dirs[3*q+2]);
    float inv = rsqrtf(fmaxf(dx*dx+dy*dy+dz*dz, 1e-24f));
    dx*=inv; dy*=inv; dz*=inv;
    float v = 0.f;
    if (lane < 12){
        float comp = (lane<4)?dx:((lane<8)?dy:dz);
        v = __sinf(comp*(float)(1<<(lane&3)));
    } else if (lane < 24){
        int l = lane-12;
        float comp = (l<4)?dx:((l<8)?dy:dz);
        v = __cosf(comp*(float)(1<<(l&3)));
    } else if (lane < 27){
        v = (lane==24)?dx:((lane==25)?dy:dz);
    }
    g_rin[(size_t)q*160 + 128 + lane] = v;
}

// ---------------- K-headB: rgb layer 2 (64->32) + sigmoid ----------------
__global__ __launch_bounds__(256) void k_headB(const float* __restrict__ rw2,
                                               const float* __restrict__ rb2,
                                               float* __restrict__ out){
    __shared__ __align__(16) float s_w2[64*32];
    __shared__ float s_b2[32];
    __shared__ float s_h[8][64];
    for (int i=threadIdx.x;i<64*32;i+=256) s_w2[i]=rw2[i];
    for (int i=threadIdx.x;i<32;i+=256) s_b2[i]=rb2[i];
    __syncthreads();

    int w=threadIdx.x>>5, lane=threadIdx.x&31;
    int q=blockIdx.x*8 + w;
    s_h[w][lane]    = g_hr[(size_t)q*64 + lane];
    s_h[w][32+lane] = g_hr[(size_t)q*64 + 32 + lane];
    __syncwarp();

    float acc = s_b2[lane];
    #pragma unroll 8
    for (int i=0;i<64;++i)
        acc = fmaf(s_h[w][i], s_w2[i*32+lane], acc);
    if (lane < 3)
        acc = 1.f/(1.f+__expf(-acc)) * 1.002f - 0.001f;
    out[RGB_OFF + (size_t)q*32 + lane] = acc;
}

// ---------------- launcher (k_knng at 4th launch -> profiled) ----------------
extern "C" void kernel_launch(void* const* d_in, const int* in_sizes, int n_in,
                              void* d_out, int out_size) {
    const float* coords = (const float*)d_in[0];
    const float* dirs   = (const float*)d_in[1];
    const float* ppos   = (const float*)d_in[2];
    const float* tpl    = (const float*)d_in[3];
    const float* emb    = (const float*)d_in[4];
    const float* pw1    = (const float*)d_in[5];
    const float* pb1    = (const float*)d_in[6];
    const float* pw2    = (const float*)d_in[7];
    const float* pb2    = (const float*)d_in[8];
    const float* fw1    = (const float*)d_in[9];
    const float* fb1    = (const float*)d_in[10];
    const float* fw2    = (const float*)d_in[11];
    const float* fb2    = (const float*)d_in[12];
    const float* fw3    = (const float*)d_in[13];
    const float* fb3    = (const float*)d_in[14];
    const float* dw     = (const float*)d_in[15];
    const float* db     = (const float*)d_in[16];
    const float* rw1    = (const float*)d_in[17];
    const float* rb1    = (const float*)d_in[18];
    const float* rw2    = (const float*)d_in[19];
    const float* rb2    = (const float*)d_in[20];
    float* out = (float*)d_out;

    float *d_h1, *d_h2, *d_h3, *d_feat, *d_pin, *d_ph1, *d_ph2, *d_rin, *d_hr;
    cudaGetSymbolAddress((void**)&d_feat, g_feat);
    cudaGetSymbolAddress((void**)&d_h1, g_h1);
    cudaGetSymbolAddress((void**)&d_h2, g_h2);
    cudaGetSymbolAddress((void**)&d_h3, g_h3);
    cudaGetSymbolAddress((void**)&d_pin, g_pin);
    cudaGetSymbolAddress((void**)&d_ph1, g_ph1);
    cudaGetSymbolAddress((void**)&d_ph2, g_ph2);
    cudaGetSymbolAddress((void**)&d_rin, g_rin);
    cudaGetSymbolAddress((void**)&d_hr, g_hr);

    k_prep<<<(NB*PB+255)/256, 256>>>(ppos);                         // 0
    k_build<<<NB, 512>>>(ppos);                                     // 1
    k_transpose<<<dim3(5,129,6), dim3(32,32)>>>(tpl);               // 2
    k_knng<<<NQ/256, 256>>>(coords, emb, out);                      // 3 <- profiled
    k_tmma<64,59,64,1><<<NR/128, 256>>>(d_pin, pw1, pb1, d_ph1);    // 4
    k_tmma<64,64,32,0><<<NR/128, 256>>>(d_ph1, pw2, pb2, d_ph2);    // 5
    k_tex<<<NQ/8, 256>>>(coords);                                   // 6
    k_wsum1<<<128, 256>>>();                                        // 7
    k_wsum2<<<1, 32>>>();                                           // 8
    k_combine<<<NQ/8, 256>>>();                                     // 9
    k_tmma<64,64,128,1><<<NQ/128, 256>>>(d_feat, fw1, fb1, d_h1);
    k_tmma<128,128,128,1><<<NQ/128, 256>>>(d_h1, fw2, fb2, d_h2);
    k_tmma<128,128,128,0><<<NQ/128, 256>>>(d_h2, fw3, fb3, d_h3);
    k_rin<<<NQ/8, 256>>>(coords, dirs, dw, db, out);
    k_tmma<160,155,64,1><<<NQ/128, 256>>>(d_rin, rw1, rb1, d_hr);
    k_headB<<<NQ/8, 256>>>(rw2, rb2, out);
}

// round 17
// speedup vs baseline: 1.0697x; 1.0697x over previous
#include <cuda_runtime.h>
#include <math.h>

#define NB 2
#define MB 16384
#define PB 5023
#define KB 4
#define CB 32
#define HPX 256
#define REG 129
#define ROFF 127
#define NQ (NB*MB)
#define NR (NQ*KB)
#define G 8
#define NC (G*G*G)

#define DENS_OFF 0
#define RGB_OFF  (NQ)
#define DIST_OFF (NQ + NQ*32)

typedef unsigned long long ull;

// ---------------- device scratch ----------------
__device__ __align__(16) float4 g_pts4[NB*PB];
__device__ __align__(16) float4 g_cellpts[NB*PB];
__device__ int g_cellstart[NB][NC+1];
__device__ __align__(16) float  g_texT[NB*3*REG*REG*CB];
__device__ __align__(16) float  g_knn_d[NQ*KB];
__device__ int    g_knn_i[NQ*KB];
__device__ float  g_wpart[128*4];
__device__ float  g_wsum[NB*KB];
__device__ __align__(16) float  g_pin[NR*64];
__device__ __align__(16) float  g_ph1[NR*64];
__device__ __align__(16) float  g_ph2[NR*32];
__device__ __align__(16) float  g_feat[NQ*64];
__device__ __align__(16) float  g_h1[NQ*128];
__device__ __align__(16) float  g_h2[NQ*128];
__device__ __align__(16) float  g_h3[NQ*128];
__device__ __align__(16) float  g_rin[NQ*160];
__device__ __align__(16) float  g_hr[NQ*64];

// ---------------- helpers ----------------
__device__ __forceinline__ unsigned f2ord(float f){
    unsigned b = __float_as_uint(f);
    return (b & 0x80000000u) ? ~b : (b | 0x80000000u);
}
__device__ __forceinline__ float ord2f(unsigned u){
    unsigned b = (u & 0x80000000u) ? (u & 0x7fffffffu) : ~u;
    return __uint_as_float(b);
}
__device__ __forceinline__ ull umin64(ull a, ull b){ return a<b?a:b; }
__device__ __forceinline__ ull umax64(ull a, ull b){ return a>b?a:b; }
__device__ __forceinline__ void insert4(ull& k0, ull& k1, ull& k2, ull& k3, ull c){
    ull mn2 = umin64(k2,c), mn1 = umin64(k1,c), mn0 = umin64(k0,c);
    k3 = umax64(k2,c); k2 = umax64(k1,mn2); k1 = umax64(k0,mn1); k0 = mn0;
}
__device__ __forceinline__ int cellof(float x){
    int c = (int)(x * (float)G);
    return min(G-1, max(0, c));
}
__device__ __forceinline__ unsigned f2tf(float f){
    unsigned r;
    asm("cvt.rna.tf32.f32 %0, %1;" : "=r"(r) : "f"(f));
    return r;
}

// ---------------- K1: pack points ----------------
__global__ void k_prep(const float* __restrict__ ppos){
    int i = blockIdx.x*blockDim.x + threadIdx.x;
    if (i < NB*PB){
        float x = ppos[3*i+0], y = ppos[3*i+1], z = ppos[3*i+2];
        g_pts4[i] = make_float4(x,y,z, x*x+y*y+z*z);
    }
}

// ---------------- K1b: build uniform grid ----------------
__global__ __launch_bounds__(512) void k_build(const float* __restrict__ ppos){
    __shared__ int s_cnt[NC];
    __shared__ int s_off[NC];
    int n = blockIdx.x, t = threadIdx.x;
    s_cnt[t] = 0;
    __syncthreads();
    for (int i = t; i < PB; i += 512){
        const float* p = ppos + (size_t)(n*PB+i)*3;
        int c = (cellof(p[2])*G + cellof(p[1]))*G + cellof(p[0]);
        atomicAdd(&s_cnt[c], 1);
    }
    __syncthreads();
    for (int ofs=1; ofs<NC; ofs<<=1){
        int add = (t >= ofs) ? s_cnt[t-ofs] : 0;
        __syncthreads();
        s_cnt[t] += add;
        __syncthreads();
    }
    s_off[t] = (t==0) ? 0 : s_cnt[t-1];
    g_cellstart[n][t+1] = s_cnt[t];
    if (t==0) g_cellstart[n][0] = 0;
    __syncthreads();
    for (int i = t; i < PB; i += 512){
        const float* p = ppos + (size_t)(n*PB+i)*3;
        float x=p[0], y=p[1], z=p[2];
        int c = (cellof(z)*G + cellof(y))*G + cellof(x);
        int pos = atomicAdd(&s_off[c], 1);
        g_cellpts[n*PB+pos] = make_float4(x,y,z, __uint_as_float((unsigned)i));
    }
}

// ---------------- grid KNN scan: smem-staged candidates, 4-wide batched ----------------
__device__ __forceinline__ void scan_block(const float4* __restrict__ s_pts,
                                           const int* __restrict__ s_cs,
                                           float cx, float cy, float cz,
                                           int qcx, int qcy, int qcz, int R,
                                           ull& k0, ull& k1, ull& k2, ull& k3){
    k0=k1=k2=k3=~0ull;
    int z0=max(qcz-R,0), z1=min(qcz+R,G-1);
    int y0=max(qcy-R,0), y1=min(qcy+R,G-1);
    int x0=max(qcx-R,0), x1=min(qcx+R,G-1);
    for (int zz=z0; zz<=z1; ++zz)
        for (int yy=y0; yy<=y1; ++yy){
            int b = (zz*G+yy)*G;
            int j  = s_cs[b+x0];
            int j1 = s_cs[b+x1+1];
            // 4-wide batched: independent loads + distance math up front,
            // dependent compare/insert chain after
            for (; j+4 <= j1; j += 4){
                float4 p0 = s_pts[j  ];
                float4 p1 = s_pts[j+1];
                float4 p2 = s_pts[j+2];
                float4 p3 = s_pts[j+3];
                float dx0=cx-p0.x, dy0=cy-p0.y, dz0=cz-p0.z;
                float dx1=cx-p1.x, dy1=cy-p1.y, dz1=cz-p1.z;
                float dx2=cx-p2.x, dy2=cy-p2.y, dz2=cz-p2.z;
                float dx3=cx-p3.x, dy3=cy-p3.y, dz3=cz-p3.z;
                float t0 = fmaf(dz0,dz0, fmaf(dy0,dy0, dx0*dx0));
                float t1 = fmaf(dz1,dz1, fmaf(dy1,dy1, dx1*dx1));
                float t2 = fmaf(dz2,dz2, fmaf(dy2,dy2, dx2*dx2));
                float t3 = fmaf(dz3,dz3, fmaf(dy3,dy3, dx3*dx3));
                ull key0 = ((ull)f2ord(t0) << 32) | __float_as_uint(p0.w);
                ull key1 = ((ull)f2ord(t1) << 32) | __float_as_uint(p1.w);
                ull key2 = ((ull)f2ord(t2) << 32) | __float_as_uint(p2.w);
                ull key3 = ((ull)f2ord(t3) << 32) | __float_as_uint(p3.w);
                if (key0 < k3) insert4(k0,k1,k2,k3,key0);
                if (key1 < k3) insert4(k0,k1,k2,k3,key1);
                if (key2 < k3) insert4(k0,k1,k2,k3,key2);
                if (key3 < k3) insert4(k0,k1,k2,k3,key3);
            }
            for (; j < j1; ++j){
                float4 p = s_pts[j];
                float ddx=cx-p.x, ddy=cy-p.y, ddz=cz-p.z;
                float t = fmaf(ddz,ddz, fmaf(ddy,ddy, ddx*ddx));
                ull key = ((ull)f2ord(t) << 32) | __float_as_uint(p.w);
                if (key < k3) insert4(k0,k1,k2,k3,key);
            }
        }
}
__device__ __forceinline__ float safe_r(float cx, float cy, float cz,
                                        int qcx, int qcy, int qcz, int R){
    const float CS = 1.f/(float)G;
    float rs = 1e30f;
    if (qcx-R > 0)   rs = fminf(rs, cx - (float)(qcx-R)*CS);
    if (qcx+R < G-1) rs = fminf(rs, (float)(qcx+R+1)*CS - cx);
    if (qcy-R > 0)   rs = fminf(rs, cy - (float)(qcy-R)*CS);
    if (qcy+R < G-1) rs = fminf(rs, (float)(qcy+R+1)*CS - cy);
    if (qcz-R > 0)   rs = fminf(rs, cz - (float)(qcz-R)*CS);
    if (qcz+R < G-1) rs = fminf(rs, (float)(qcz+R+1)*CS - cz);
    return rs;
}

// ---------------- K3: grid KNN + fused point-MLP input-row build ----------------
__global__ __launch_bounds__(256) void k_knng(const float* __restrict__ coords,
                                              const float* __restrict__ emb,
                                              float* __restrict__ out){
    extern __shared__ char sm[];
    float4* s_pts = (float4*)sm;
    int*    s_cs  = (int*)(sm + PB*sizeof(float4));
    int n = blockIdx.x >> 6;
    int t = threadIdx.x;
    for (int i = t; i < PB; i += 256) s_pts[i] = g_cellpts[n*PB+i];
    for (int i = t; i <= NC; i += 256) s_cs[i] = g_cellstart[n][i];
    __syncthreads();

    int q = blockIdx.x*256 + t;
    float cx = coords[3*q+0], cy = coords[3*q+1], cz = coords[3*q+2];
    int qcx = cellof(cx), qcy = cellof(cy), qcz = cellof(cz);

    ull k0,k1,k2,k3;
    int R = 1;
    scan_block(s_pts, s_cs, cx,cy,cz, qcx,qcy,qcz, R, k0,k1,k2,k3);
    float d3 = ord2f((unsigned)(k3 >> 32));
    float rs = safe_r(cx,cy,cz, qcx,qcy,qcz, R);
    while (!(d3 <= rs*rs) && R < G){
        ++R;
        scan_block(s_pts, s_cs, cx,cy,cz, qcx,qcy,qcz, R, k0,k1,k2,k3);
        d3 = ord2f((unsigned)(k3 >> 32));
        rs = safe_r(cx,cy,cz, qcx,qcy,qcz, R);
    }

    ull rr[4] = {k0,k1,k2,k3};
    #pragma unroll
    for (int r=0; r<4; ++r){
        float d  = ord2f((unsigned)(rr[r] >> 32));
        int idx  = (int)(unsigned)rr[r];
        g_knn_d[q*4+r]  = d;
        g_knn_i[q*4+r]  = idx;
        out[DIST_OFF + q*4+r] = d;

        float4 p = __ldg(&g_pts4[n*PB + idx]);
        float rx = cx-p.x, ry = cy-p.y, rz = cz-p.z;
        float inv = rsqrtf(fmaxf(rx*rx+ry*ry+rz*rz, 1e-24f));
        rx *= inv; ry *= inv; rz *= inv;
        float* dst = g_pin + (size_t)(q*4+r)*64;
        const float4* e4 = (const float4*)(emb + (size_t)idx*32);
        #pragma unroll
        for (int i=0;i<8;++i) ((float4*)dst)[i] = __ldg(&e4[i]);
        float comp[3] = {rx,ry,rz};
        #pragma unroll
        for (int c=0;c<3;++c){
            float base = comp[c];
            #pragma unroll
            for (int f=0;f<4;++f){
                float a = base * (float)(1<<f);
                dst[32 + c*4+f] = __sinf(a);
                dst[44 + c*4+f] = __cosf(a);
            }
        }
        dst[56]=rx; dst[57]=ry; dst[58]=rz;
        dst[59]=0.f; dst[60]=0.f; dst[61]=0.f; dst[62]=0.f; dst[63]=0.f;
    }
}

// ---------------- K-TMMA: tf32 tensor-core GEMM ----------------
template<int I, int IW, int O, int MODE>
__global__ __launch_bounds__(256) void k_tmma(const float* __restrict__ A,
                                              const float* __restrict__ W,
                                              const float* __restrict__ Bv,
                                              float* __restrict__ Out){
    const int SA = 36;
    const int SW = O + 8;
    const int NF = O/8;
    __shared__ __align__(16) unsigned s_a[128*SA];
    __shared__ __align__(16) unsigned s_w[32*SW];
    __shared__ float s_b[O];
    const int t = threadIdx.x;
    const int w = t >> 5, lane = t & 31;
    const int grp = lane >> 2, tig = lane & 3;
    for (int i=t;i<O;i+=256) s_b[i]=Bv[i];

    float c[NF][4];
    #pragma unroll
    for (int nf=0;nf<NF;++nf){ c[nf][0]=0.f; c[nf][1]=0.f; c[nf][2]=0.f; c[nf][3]=0.f; }

    int rb = blockIdx.x * 128;

    for (int kc=0; kc<I/32; ++kc){
        __syncthreads();
        #pragma unroll
        for (int r=0;r<4;++r){
            int e = r*256 + t;
            int row = e >> 3, v = e & 7;
            float4 av = __ldg((const float4*)(A + (size_t)(rb+row)*I + kc*32) + v);
            *(uint4*)&s_a[row*SA + v*4] =
                make_uint4(f2tf(av.x), f2tf(av.y), f2tf(av.z), f2tf(av.w));
        }
        #pragma unroll
        for (int e=t; e<32*O/4; e+=256){
            int row = (e*4)/O;
            int col = (e*4)%O;
            int wrow = kc*32 + row;
            float4 wv = make_float4(0.f,0.f,0.f,0.f);
            if (wrow < IW) wv = __ldg((const float4*)(W + (size_t)wrow*O + col));
            *(uint4*)&s_w[row*SW + col] =
                make_uint4(f2tf(wv.x), f2tf(wv.y), f2tf(wv.z), f2tf(wv.w));
        }
        __syncthreads();
        #pragma unroll
        for (int k8=0;k8<4;++k8){
            unsigned a0 = s_a[(w*16+grp  )*SA + k8*8+tig  ];
            unsigned a1 = s_a[(w*16+grp+8)*SA + k8*8+tig  ];
            unsigned a2 = s_a[(w*16+grp  )*SA + k8*8+tig+4];
            unsigned a3 = s_a[(w*16+grp+8)*SA + k8*8+tig+4];
            #pragma unroll
            for (int nf=0;nf<NF;++nf){
                unsigned b0 = s_w[(k8*8+tig  )*SW + nf*8+grp];
                unsigned b1 = s_w[(k8*8+tig+4)*SW + nf*8+grp];
                asm volatile("mma.sync.aligned.m16n8k8.row.col.f32.tf32.tf32.f32 "
                    "{%0,%1,%2,%3}, {%4,%5,%6,%7}, {%8,%9}, {%0,%1,%2,%3};"
                    : "+f"(c[nf][0]),"+f"(c[nf][1]),"+f"(c[nf][2]),"+f"(c[nf][3])
                    : "r"(a0),"r"(a1),"r"(a2),"r"(a3),"r"(b0),"r"(b1));
            }
        }
    }
    int r0 = rb + w*16 + grp;
    int r1 = r0 + 8;
    #pragma unroll
    for (int nf=0;nf<NF;++nf){
        int o = nf*8 + 2*tig;
        float bx = s_b[o], by = s_b[o+1];
        float v0=c[nf][0]+bx, v1=c[nf][1]+by, v2=c[nf][2]+bx, v3=c[nf][3]+by;
        if (MODE==1){ v0=fmaxf(v0,0.f); v1=fmaxf(v1,0.f); v2=fmaxf(v2,0.f); v3=fmaxf(v3,0.f); }
        *(float2*)&Out[(size_t)r0*O+o] = make_float2(v0,v1);
        *(float2*)&Out[(size_t)r1*O+o] = make_float2(v2,v3);
    }
}

// ---------------- K4: wsum ----------------
__global__ __launch_bounds__(256) void k_wsum1(){
    int t = threadIdx.x;
    int base = blockIdx.x * 1024;
    float acc = 0.f;
    #pragma unroll
    for (int r=0;r<4;++r) acc += 1.0f / g_knn_d[base + t + r*256];
    acc += __shfl_xor_sync(0xffffffffu, acc, 4);
    acc += __shfl_xor_sync(0xffffffffu, acc, 8);
    acc += __shfl_xor_sync(0xffffffffu, acc, 16);
    __shared__ float s_p[8][4];
    int w = t >> 5, l = t & 31;
    if (l < 4) s_p[w][l] = acc;
    __syncthreads();
    if (t < 4){
        float s = 0.f;
        #pragma unroll
        for (int w2=0; w2<8; ++w2) s += s_p[w2][t];
        g_wpart[blockIdx.x*4 + t] = s;
    }
}
__global__ void k_wsum2(){
    int t = threadIdx.x;
    if (t < NB*KB){
        int n = t >> 2, kk = t & 3;
        float s = 0.f;
        for (int b = n*64; b < n*64+64; ++b) s += g_wpart[b*4 + kk];
        g_wsum[t] = s;
    }
}

// ---------------- K-combine ----------------
__global__ __launch_bounds__(256) void k_combine(){
    int w = threadIdx.x >> 5, lane = threadIdx.x & 31;
    int q = blockIdx.x*8 + w;
    int n = q / MB;
    float acc = 0.f;
    #pragma unroll
    for (int k=0;k<4;++k){
        float d  = g_knn_d[q*4+k];
        float wk = (1.0f/d) * (1.0f/g_wsum[n*KB+k]);
        acc = fmaf(g_ph2[(size_t)(q*4+k)*32 + lane], wk, acc);
    }
    g_feat[q*64 + 32 + lane] = acc;
}

// ---------------- K2: transpose triplane region ----------------
__global__ void k_transpose(const float* __restrict__ tpl){
    __shared__ float tile[32][33];
    int z  = blockIdx.z;
    int ry = blockIdx.y;
    int xt = blockIdx.x*32;
    int tx = threadIdx.x, ty = threadIdx.y;
    int gx = xt + tx;
    if (gx < REG)
        tile[ty][tx] = tpl[(z*CB + ty)*(HPX*HPX) + (ROFF+ry)*HPX + (ROFF+gx)];
    __syncthreads();
    int xo = xt + ty;
    if (xo < REG)
        g_texT[((z*REG + ry)*REG + xo)*CB + tx] = tile[tx][ty];
}

// ---------------- K5: triplane sampling ----------------
__global__ __launch_bounds__(256) void k_tex(const float* __restrict__ coords){
    int q = blockIdx.x*8 + (threadIdx.x >> 5);
    int lane = threadIdx.x & 31;
    int n = q / MB;
    float c0 = __ldg(&coords[3*q+0]);
    float c1 = __ldg(&coords[3*q+1]);
    float c2 = __ldg(&coords[3*q+2]);
    float gxs[3] = {c0, c0, c2};
    float gys[3] = {c1, c2, c0};
    float acc = 0.f;
    #pragma unroll
    for (int pl=0; pl<3; ++pl){
        float x = (gxs[pl]+1.f)*(HPX*0.5f) - 0.5f;
        float y = (gys[pl]+1.f)*(HPX*0.5f) - 0.5f;
        float fx0 = floorf(x), fy0 = floorf(y);
        int ix0 = (int)fx0, iy0 = (int)fy0;
        float wx1 = x - fx0, wx0 = 1.f - wx1;
        float wy1 = y - fy0, wy0 = 1.f - wy1;
        const float* base = g_texT + (size_t)(n*3 + pl)*REG*REG*CB;
        #pragma unroll
        for (int dy=0; dy<2; ++dy)
            #pragma unroll
            for (int dx=0; dx<2; ++dx){
                int ix = ix0 + dx, iy = iy0 + dy;
                bool v = (ix>=0) & (ix<HPX) & (iy>=0) & (iy<HPX);
                int rx = min(max(ix-ROFF,0), REG-1);
                int ry = min(max(iy-ROFF,0), REG-1);
                float w = (dx?wx1:wx0) * (dy?wy1:wy0) * (v?1.f:0.f);
                acc = fmaf(w, base[(ry*REG + rx)*CB + lane], acc);
            }
    }
    g_feat[q*64 + lane] = acc * (1.f/3.f);
}

// ---------------- K-rin: build rgb input rows [NQ,160] + density head ----------------
__global__ __launch_bounds__(256) void k_rin(const float* __restrict__ coords,
                                             const float* __restrict__ dirs,
                                             const float* __restrict__ dw,
                                             const float* __restrict__ db,
                                             float* __restrict__ out){
    int w = threadIdx.x >> 5, lane = threadIdx.x & 31;
    int q = blockIdx.x*8 + w;

    float4 f4 = *(const float4*)&g_h3[(size_t)q*128 + lane*4];
    *(float4*)&g_rin[(size_t)q*160 + lane*4] = f4;

    float part = f4.x*__ldg(&dw[lane*4+0]) + f4.y*__ldg(&dw[lane*4+1])
               + f4.z*__ldg(&dw[lane*4+2]) + f4.w*__ldg(&dw[lane*4+3]);
    #pragma unroll
    for (int s=16;s>0;s>>=1) part += __shfl_xor_sync(0xffffffffu, part, s);
    if (lane == 0){
        float x = 10.f*(part + __ldg(&db[0]));
        float sp = (x > 20.f) ? x : log1pf(__expf(x));
        float c0=__ldg(&coords[3*q+0]), c1=__ldg(&coords[3*q+1]), c2=__ldg(&coords[3*q+2]);
        bool sel = (c0>-1.f)&&(c0<1.f)&&(c1>-1.f)&&(c1<1.f)&&(c2>-1.f)&&(c2<1.f);
        float raw = (sp*0.1f) * (sel?1.f:0.f);
        out[DENS_OFF + q] = 1.f - __expf(-raw);
    }

    float dx=__ldg(&dirs[3*q+0]), dy=__ldg(&dirs[3*q+1]), dz=__ldg(&dirs[3*q+2]);
    float inv = rsqrtf(fmaxf(dx*dx+dy*dy+dz*dz, 1e-24f));
    dx*=inv; dy*=inv; dz*=inv;
    float v = 0.f;
    if (lane < 12){
        float comp = (lane<4)?dx:((lane<8)?dy:dz);
        v = __sinf(comp*(float)(1<<(lane&3)));
    } else if (lane < 24){
        int l = lane-12;
        float comp = (l<4)?dx:((l<8)?dy:dz);
        v = __cosf(comp*(float)(1<<(l&3)));
    } else if (lane < 27){
        v = (lane==24)?dx:((lane==25)?dy:dz);
    }
    g_rin[(size_t)q*160 + 128 + lane] = v;
}

// ---------------- K-headB: rgb layer 2 (64->32) + sigmoid ----------------
__global__ __launch_bounds__(256) void k_headB(const float* __restrict__ rw2,
                                               const float* __restrict__ rb2,
                                               float* __restrict__ out){
    __shared__ __align__(16) float s_w2[64*32];
    __shared__ float s_b2[32];
    __shared__ float s_h[8][64];
    for (int i=threadIdx.x;i<64*32;i+=256) s_w2[i]=rw2[i];
    for (int i=threadIdx.x;i<32;i+=256) s_b2[i]=rb2[i];
    __syncthreads();

    int w=threadIdx.x>>5, lane=threadIdx.x&31;
    int q=blockIdx.x*8 + w;
    s_h[w][lane]    = g_hr[(size_t)q*64 + lane];
    s_h[w][32+lane] = g_hr[(size_t)q*64 + 32 + lane];
    __syncwarp();

    float acc = s_b2[lane];
    #pragma unroll 8
    for (int i=0;i<64;++i)
        acc = fmaf(s_h[w][i], s_w2[i*32+lane], acc);
    if (lane < 3)
        acc = 1.f/(1.f+__expf(-acc)) * 1.002f - 0.001f;
    out[RGB_OFF + (size_t)q*32 + lane] = acc;
}

// ---------------- launcher (k_knng at 4th launch -> profiled) ----------------
extern "C" void kernel_launch(void* const* d_in, const int* in_sizes, int n_in,
                              void* d_out, int out_size) {
    const float* coords = (const float*)d_in[0];
    const float* dirs   = (const float*)d_in[1];
    const float* ppos   = (const float*)d_in[2];
    const float* tpl    = (const float*)d_in[3];
    const float* emb    = (const float*)d_in[4];
    const float* pw1    = (const float*)d_in[5];
    const float* pb1    = (const float*)d_in[6];
    const float* pw2    = (const float*)d_in[7];
    const float* pb2    = (const float*)d_in[8];
    const float* fw1    = (const float*)d_in[9];
    const float* fb1    = (const float*)d_in[10];
    const float* fw2    = (const float*)d_in[11];
    const float* fb2    = (const float*)d_in[12];
    const float* fw3    = (const float*)d_in[13];
    const float* fb3    = (const float*)d_in[14];
    const float* dw     = (const float*)d_in[15];
    const float* db     = (const float*)d_in[16];
    const float* rw1    = (const float*)d_in[17];
    const float* rb1    = (const float*)d_in[18];
    const float* rw2    = (const float*)d_in[19];
    const float* rb2    = (const float*)d_in[20];
    float* out = (float*)d_out;

    float *d_h1, *d_h2, *d_h3, *d_feat, *d_pin, *d_ph1, *d_ph2, *d_rin, *d_hr;
    cudaGetSymbolAddress((void**)&d_feat, g_feat);
    cudaGetSymbolAddress((void**)&d_h1, g_h1);
    cudaGetSymbolAddress((void**)&d_h2, g_h2);
    cudaGetSymbolAddress((void**)&d_h3, g_h3);
    cudaGetSymbolAddress((void**)&d_pin, g_pin);
    cudaGetSymbolAddress((void**)&d_ph1, g_ph1);
    cudaGetSymbolAddress((void**)&d_ph2, g_ph2);
    cudaGetSymbolAddress((void**)&d_rin, g_rin);
    cudaGetSymbolAddress((void**)&d_hr, g_hr);

    const int KNN_SMEM = PB*sizeof(float4) + (NC+1)*sizeof(int);
    cudaFuncSetAttribute(k_knng, cudaFuncAttributeMaxDynamicSharedMemorySize, KNN_SMEM);

    k_prep<<<(NB*PB+255)/256, 256>>>(ppos);                         // 0
    k_build<<<NB, 512>>>(ppos);                                     // 1
    k_transpose<<<dim3(5,129,6), dim3(32,32)>>>(tpl);               // 2
    k_knng<<<NQ/256, 256, KNN_SMEM>>>(coords, emb, out);            // 3 <- profiled
    k_tmma<64,59,64,1><<<NR/128, 256>>>(d_pin, pw1, pb1, d_ph1);    // 4
    k_tmma<64,64,32,0><<<NR/128, 256>>>(d_ph1, pw2, pb2, d_ph2);    // 5
    k_tex<<<NQ/8, 256>>>(coords);                                   // 6
    k_wsum1<<<128, 256>>>();                                        // 7
    k_wsum2<<<1, 32>>>();                                           // 8
    k_combine<<<NQ/8, 256>>>();                                     // 9
    k_tmma<64,64,128,1><<<NQ/128, 256>>>(d_feat, fw1, fb1, d_h1);
    k_tmma<128,128,128,1><<<NQ/128, 256>>>(d_h1, fw2, fb2, d_h2);
    k_tmma<128,128,128,0><<<NQ/128, 256>>>(d_h2, fw3, fb3, d_h3);
    k_rin<<<NQ/8, 256>>>(coords, dirs, dw, db, out);
    k_tmma<160,155,64,1><<<NQ/128, 256>>>(d_rin, rw1, rb1, d_hr);
    k_headB<<<NQ/8, 256>>>(rw2, rb2, out);
}